// round 13
// baseline (speedup 1.0000x reference)
#include <cuda_runtime.h>
#include <cstdint>

#define Bsz 4096
#define Hdim 1024
#define Kmix 10
#define Lw 64
#define Vv 80
#define N3K 30
#define CH 8                  // batch rows per chunk
#define NCHUNK (Bsz / CH)     // 512 chunks
#define GRID 148              // persistent blocks (1/SM)
#define NTHR 256

typedef unsigned long long ull;

// packed dual-FMA on {lo,hi} fp32 pairs
#define FFMA2(d, a, b, c) \
    asm("fma.rn.f32x2 %0, %1, %2, %3;" : "=l"(d) : "l"(a), "l"(b), "l"(c))

// ---- dynamic smem layout (bytes) ----
#define OFF_S0   0            // chars sub-buffer 0: 4 rows  (81920 B)
#define OFF_S1   81920        // chars sub-buffer 1: 4 rows  (81920 B)
#define OFF_X    163840       // x chunk: 8 rows x 1024      (32768 B)
#define OFF_PART 196608       // GEMM partials 8w x 8r x 32  (8192 B)
#define OFF_SE   204800       // exp params 8r x 32          (1024 B)
#define OFF_PHI  205824       // phi 8r x 64                 (2048 B)
#define OFF_MBAR 207872       // 3 mbarriers
#define SMEM_BYTES 207936

#define XBYTES  (CH * Hdim * 4)          // 32768
#define SBYTES  (4 * Lw * Vv * 4)        // 81920

__device__ __forceinline__ uint32_t smem_u32(const void* p) {
    uint32_t a;
    asm("{ .reg .u64 t; cvta.to.shared.u64 t, %1; cvt.u32.u64 %0, t; }"
        : "=r"(a) : "l"(p));
    return a;
}

#define MBAR_INIT(m, n) \
    asm volatile("mbarrier.init.shared.b64 [%0], %1;" :: "r"(m), "r"(n) : "memory")
#define MBAR_EXPECT(m, bytes) \
    asm volatile("mbarrier.arrive.expect_tx.shared.b64 _, [%0], %1;" \
                 :: "r"(m), "r"(bytes) : "memory")
#define BULK_G2S(dst, src, bytes, m) \
    asm volatile("cp.async.bulk.shared::cluster.global.mbarrier::complete_tx::bytes " \
                 "[%0], [%1], %2, [%3];" \
                 :: "r"(dst), "l"(src), "r"(bytes), "r"(m) : "memory")
#define MBAR_WAIT(m, parity) do {                                            \
    asm volatile("{\n\t.reg .pred P;\n\t"                                    \
        "WL_%=:\n\t"                                                         \
        "mbarrier.try_wait.parity.acquire.cta.shared::cta.b64 P, [%0], %1, 0x989680;\n\t" \
        "@P bra.uni WD_%=;\n\t"                                              \
        "bra.uni WL_%=;\n\t"                                                 \
        "WD_%=:\n\t}"                                                        \
        :: "r"(m), "r"(parity) : "memory"); } while (0)

// ---------------------------------------------------------------------------
// Persistent pipelined kernel: per 8-row chunk, DMA (x + chars) overlaps the
// fp32 GEMM; window phase consumes chars from smem and immediately re-issues
// the next chunk's DMA into the freed buffer.
// ---------------------------------------------------------------------------
__global__ __launch_bounds__(NTHR) void fused_pipe_kernel(
    const float* __restrict__ x, const float* __restrict__ chars,
    const float* __restrict__ W, const float* __restrict__ bias,
    float* __restrict__ out)
{
    extern __shared__ char dyn[];
    float* s0   = (float*)(dyn + OFF_S0);
    float* s1   = (float*)(dyn + OFF_S1);
    float* xs   = (float*)(dyn + OFF_X);
    float* part = (float*)(dyn + OFF_PART);
    float* se   = (float*)(dyn + OFF_SE);
    float* phi  = (float*)(dyn + OFF_PHI);

    const uint32_t mb_x  = smem_u32(dyn + OFF_MBAR);
    const uint32_t mb_s0 = mb_x + 8;
    const uint32_t mb_s1 = mb_x + 16;
    const uint32_t s0a = smem_u32(s0), s1a = smem_u32(s1), xsa = smem_u32(xs);

    const int tid  = threadIdx.x;
    const int lane = tid & 31;
    const int w    = tid >> 5;
    const int bid  = blockIdx.x;
    // 512 = 68*4 + 80*3 chunks
    const int nch  = (bid < 68) ? 4 : 3;

    if (tid == 0) { MBAR_INIT(mb_x, 1); MBAR_INIT(mb_s0, 1); MBAR_INIT(mb_s1, 1); }
    __syncthreads();

    for (int i = 0; i < nch; ++i) {
        const int c   = bid + i * GRID;
        const int b0  = c * CH;
        const int par = i & 1;

        if (i == 0 && tid == 0) {
            MBAR_EXPECT(mb_x, XBYTES);
            BULK_G2S(xsa, x + (size_t)b0 * Hdim, XBYTES, mb_x);
            MBAR_EXPECT(mb_s0, SBYTES);
            BULK_G2S(s0a, chars + (size_t)b0 * Lw * Vv, SBYTES, mb_s0);
            MBAR_EXPECT(mb_s1, SBYTES);
            BULK_G2S(s1a, chars + (size_t)(b0 + 4) * Lw * Vv, SBYTES, mb_s1);
        }

        // ---- Phase 1: GEMM partials (x from smem, W from L1/L2) ------------
        MBAR_WAIT(mb_x, par);
        ull acc[CH];
        #pragma unroll
        for (int r = 0; r < CH; ++r) acc[r] = 0ull;

        const int  h0     = w * 128;
        const bool kvalid = (lane < N3K);

        #pragma unroll 2
        for (int hh = 0; hh < 128; hh += 4) {
            const int h = h0 + hh;
            float w0 = kvalid ? W[(size_t)(h + 0) * N3K + lane] : 0.f;
            float w1 = kvalid ? W[(size_t)(h + 1) * N3K + lane] : 0.f;
            float w2 = kvalid ? W[(size_t)(h + 2) * N3K + lane] : 0.f;
            float w3 = kvalid ? W[(size_t)(h + 3) * N3K + lane] : 0.f;
            ull wp01, wp23;
            asm("mov.b64 %0, {%1, %2};" : "=l"(wp01)
                : "r"(__float_as_uint(w0)), "r"(__float_as_uint(w1)));
            asm("mov.b64 %0, {%1, %2};" : "=l"(wp23)
                : "r"(__float_as_uint(w2)), "r"(__float_as_uint(w3)));
            #pragma unroll
            for (int rg = 0; rg < 2; ++rg) {
                ulonglong2 xv[4];
                #pragma unroll
                for (int j = 0; j < 4; ++j)
                    xv[j] = *(const ulonglong2*)&xs[(rg * 4 + j) * Hdim + h];
                #pragma unroll
                for (int j = 0; j < 4; ++j) {
                    FFMA2(acc[rg * 4 + j], xv[j].x, wp01, acc[rg * 4 + j]);
                    FFMA2(acc[rg * 4 + j], xv[j].y, wp23, acc[rg * 4 + j]);
                }
            }
        }
        #pragma unroll
        for (int r = 0; r < CH; ++r) {
            float lo = __uint_as_float((unsigned)(acc[r] & 0xFFFFFFFFull));
            float hi = __uint_as_float((unsigned)(acc[r] >> 32));
            part[(w * CH + r) * 32 + lane] = lo + hi;
        }
        __syncthreads();

        // x buffer free -> prefetch next chunk's x (overlaps rest of chunk)
        if (tid == 0 && i + 1 < nch) {
            MBAR_EXPECT(mb_x, XBYTES);
            BULK_G2S(xsa, x + (size_t)(b0 + GRID * CH) * Hdim, XBYTES, mb_x);
        }

        // ---- Phase 2: reduce + bias + exp (240 items) ----------------------
        if (tid < CH * N3K) {
            const int r = tid / N3K, k = tid - r * N3K;
            float s = 0.f;
            #pragma unroll
            for (int ww = 0; ww < 8; ++ww) s += part[(ww * CH + r) * 32 + k];
            se[r * 32 + k] = expf(s + bias[k]);
        }
        __syncthreads();

        // ---- Phase 3: phi (512 items = 8r x 64l) ---------------------------
        #pragma unroll
        for (int it = 0; it < 2; ++it) {
            const int idx = tid + it * NTHR;
            const int r = idx >> 6, l = idx & 63;
            const float u = (float)l;
            float s = 0.f;
            #pragma unroll
            for (int k = 0; k < Kmix; ++k) {
                float d = se[r * 32 + 20 + k] - u;
                s += se[r * 32 + k] * expf(-se[r * 32 + 10 + k] * d * d);
            }
            phi[r * 64 + l] = s;
        }
        __syncthreads();

        // ---- Phase 4a: window rows b0..b0+3 from s0 ------------------------
        MBAR_WAIT(mb_s0, par);
        if (tid < 80) {
            const int r4 = tid / 20, v4 = tid % 20;
            float4 a = make_float4(0.f, 0.f, 0.f, 0.f);
            #pragma unroll 8
            for (int l = 0; l < Lw; ++l) {
                const float  p  = phi[r4 * 64 + l];
                const float4 cv = *(const float4*)&s0[(r4 * Lw + l) * Vv + v4 * 4];
                a.x += p * cv.x;  a.y += p * cv.y;
                a.z += p * cv.z;  a.w += p * cv.w;
            }
            *(float4*)&out[(size_t)(b0 + r4) * Vv + v4 * 4] = a;
        }
        __syncthreads();   // s0 fully consumed
        if (tid == 0 && i + 1 < nch) {
            MBAR_EXPECT(mb_s0, SBYTES);
            BULK_G2S(s0a, chars + (size_t)(b0 + GRID * CH) * Lw * Vv, SBYTES, mb_s0);
        }

        // ---- Phase 4b: window rows b0+4..b0+7 from s1 ----------------------
        MBAR_WAIT(mb_s1, par);
        if (tid < 80) {
            const int r4 = tid / 20, v4 = tid % 20;
            float4 a = make_float4(0.f, 0.f, 0.f, 0.f);
            #pragma unroll 8
            for (int l = 0; l < Lw; ++l) {
                const float  p  = phi[(4 + r4) * 64 + l];
                const float4 cv = *(const float4*)&s1[(r4 * Lw + l) * Vv + v4 * 4];
                a.x += p * cv.x;  a.y += p * cv.y;
                a.z += p * cv.z;  a.w += p * cv.w;
            }
            *(float4*)&out[(size_t)(b0 + 4 + r4) * Vv + v4 * 4] = a;
        }
        __syncthreads();   // s1 fully consumed
        if (tid == 0 && i + 1 < nch) {
            MBAR_EXPECT(mb_s1, SBYTES);
            BULK_G2S(s1a, chars + (size_t)(b0 + GRID * CH + 4) * Lw * Vv, SBYTES, mb_s1);
        }
    }
}

// ---------------------------------------------------------------------------
extern "C" void kernel_launch(void* const* d_in, const int* in_sizes, int n_in,
                              void* d_out, int out_size) {
    const float* x     = (const float*)d_in[0];   // [4096, 1024]
    const float* chars = (const float*)d_in[1];   // [4096, 64, 80]
    const float* W     = (const float*)d_in[2];   // [1024, 30]
    const float* bvec  = (const float*)d_in[3];   // [30]
    float*       out   = (float*)d_out;           // [4096, 80]

    cudaFuncSetAttribute(fused_pipe_kernel,
                         cudaFuncAttributeMaxDynamicSharedMemorySize, SMEM_BYTES);
    fused_pipe_kernel<<<GRID, NTHR, SMEM_BYTES>>>(x, chars, W, bvec, out);
}

// round 16
// speedup vs baseline: 1.5049x; 1.5049x over previous
#include <cuda_runtime.h>

#define Bsz 4096
#define Hdim 1024
#define Kmix 10
#define Lw 64
#define Vv 80
#define N3K 30
#define Rrows 8
#define NBLK (Bsz / Rrows)   // 512 blocks
#define NTHR 256

typedef unsigned long long ull;

// phi[b][l], written by kernel A, read by kernel B (1 MB)
__device__ float g_phi[Bsz * Lw];

// packed dual-FMA: d = a*b + c elementwise on {lo,hi} fp32 pairs
#define FFMA2(d, a, b, c) \
    asm("fma.rn.f32x2 %0, %1, %2, %3;" : "=l"(d) : "l"(a), "l"(b), "l"(c))

// ---------------------------------------------------------------------------
// Kernel A: x@W + b -> exp -> mixture -> phi.
// 512 blocks x 256 threads, 8 batch rows/block, occ 4 (41KB smem, <=64 regs).
// Warp w owns h-slice [w*128,(w+1)*128), lane = k. Staged x read as
// broadcast LDS.128 (packed {x[h],x[h+1]} pairs), fma.rn.f32x2.
// Co-resident CTAs share W slices via L1. Triggers PDL at entry so kernel B
// can pre-launch into the SM thread-slack and prefetch chars during A.
// ---------------------------------------------------------------------------
__global__ __launch_bounds__(NTHR, 4) void gemm_phi_kernel(
    const float* __restrict__ x, const float* __restrict__ W,
    const float* __restrict__ bias)
{
    __shared__ float4 xs4[Rrows * 256];        // 32KB staged x
    __shared__ float  part[8 * Rrows * 32];    // 8KB per-slice partials
    __shared__ float  se[Rrows * 32];          // 1KB

    cudaTriggerProgrammaticLaunchCompletion();

    const int tid  = threadIdx.x;
    const int lane = tid & 31;
    const int w    = tid >> 5;
    const int b0   = blockIdx.x * Rrows;

    // ---- Stage x: fully coalesced (8 float4 per thread) --------------------
    {
        const float4* xg = (const float4*)(x + (size_t)b0 * Hdim);
        #pragma unroll
        for (int j = 0; j < 8; ++j)
            xs4[tid + j * NTHR] = xg[tid + j * NTHR];
    }
    __syncthreads();

    // ---- Phase 1: packed-FMA GEMM partials ---------------------------------
    ull acc[Rrows];
    #pragma unroll
    for (int r = 0; r < Rrows; ++r) acc[r] = 0ull;

    const int  h0     = w * 128;
    const bool kvalid = (lane < N3K);

    #pragma unroll 2
    for (int hh = 0; hh < 128; hh += 4) {
        const int h  = h0 + hh;
        const int c4 = h >> 2;
        float w0 = kvalid ? W[(size_t)(h + 0) * N3K + lane] : 0.f;
        float w1 = kvalid ? W[(size_t)(h + 1) * N3K + lane] : 0.f;
        float w2 = kvalid ? W[(size_t)(h + 2) * N3K + lane] : 0.f;
        float w3 = kvalid ? W[(size_t)(h + 3) * N3K + lane] : 0.f;
        ull wp01, wp23;
        asm("mov.b64 %0, {%1, %2};" : "=l"(wp01)
            : "r"(__float_as_uint(w0)), "r"(__float_as_uint(w1)));
        asm("mov.b64 %0, {%1, %2};" : "=l"(wp23)
            : "r"(__float_as_uint(w2)), "r"(__float_as_uint(w3)));
        #pragma unroll
        for (int rg = 0; rg < Rrows / 4; ++rg) {
            ulonglong2 xv[4];
            #pragma unroll
            for (int i = 0; i < 4; ++i)
                xv[i] = *(const ulonglong2*)&xs4[(rg * 4 + i) * 256 + c4];
            #pragma unroll
            for (int i = 0; i < 4; ++i) {
                FFMA2(acc[rg * 4 + i], xv[i].x, wp01, acc[rg * 4 + i]);
                FFMA2(acc[rg * 4 + i], xv[i].y, wp23, acc[rg * 4 + i]);
            }
        }
    }
    #pragma unroll
    for (int r = 0; r < Rrows; ++r) {
        float lo = __uint_as_float((unsigned)(acc[r] & 0xFFFFFFFFull));
        float hi = __uint_as_float((unsigned)(acc[r] >> 32));
        part[(w * Rrows + r) * 32 + lane] = lo + hi;
    }
    __syncthreads();

    // ---- Phase 2: reduce + bias + exp (240 items) --------------------------
    if (tid < Rrows * N3K) {
        const int r = tid / N3K, k = tid - r * N3K;
        float s = 0.f;
        #pragma unroll
        for (int ww = 0; ww < 8; ++ww) s += part[(ww * Rrows + r) * 32 + k];
        se[r * 32 + k] = expf(s + bias[k]);
    }
    __syncthreads();

    // ---- Phase 3: phi -> global (512 items = 8r x 64l) ---------------------
    #pragma unroll
    for (int i = 0; i < 2; ++i) {
        const int idx = tid + i * NTHR;
        const int r = idx >> 6, l = idx & 63;
        const float u = (float)l;
        float s = 0.f;
        #pragma unroll
        for (int k = 0; k < Kmix; ++k) {
            float d = se[r * 32 + 20 + k] - u;
            s += se[r * 32 + k] * expf(-se[r * 32 + 10 + k] * d * d);
        }
        g_phi[(size_t)(b0 + r) * Lw + l] = s;
    }
}

// ---------------------------------------------------------------------------
// Kernel B: out[b] = phi[b] @ chars[b].  4096 blocks x 160 threads.
// Launched with programmatic stream serialization: blocks start during A,
// issue their 8 float4 chars prefetches, THEN wait on A's completion
// (cudaGridDependencySynchronize) before touching g_phi. The prefetched
// DRAM traffic hides under A's compute.
// ---------------------------------------------------------------------------
__global__ __launch_bounds__(160) void window_kernel(const float* __restrict__ chars,
                                                     float* __restrict__ out) {
    __shared__ float  phi_s[Lw];
    __shared__ float4 part[8][20];

    const int b   = blockIdx.x;
    const int tid = threadIdx.x;
    const int v4  = tid % 20;
    const int g   = tid / 20;

    // Prefetch this thread's 8 char float4s (independent of kernel A)
    const float4* ch = (const float4*)(chars + (size_t)b * Lw * Vv);
    float4 c[8];
    #pragma unroll
    for (int i = 0; i < 8; ++i)
        c[i] = ch[(g * 8 + i) * (Vv / 4) + v4];

    // Wait for kernel A's g_phi writes to be visible
    cudaGridDependencySynchronize();

    if (tid < Lw)
        phi_s[tid] = g_phi[(size_t)b * Lw + tid];
    __syncthreads();

    float4 acc = make_float4(0.f, 0.f, 0.f, 0.f);
    #pragma unroll
    for (int i = 0; i < 8; ++i) {
        float p = phi_s[g * 8 + i];
        acc.x += p * c[i].x;  acc.y += p * c[i].y;
        acc.z += p * c[i].z;  acc.w += p * c[i].w;
    }
    part[g][v4] = acc;
    __syncthreads();

    if (tid < 20) {
        float4 s = part[0][tid];
        #pragma unroll
        for (int g2 = 1; g2 < 8; ++g2) {
            float4 p = part[g2][tid];
            s.x += p.x;  s.y += p.y;  s.z += p.z;  s.w += p.w;
        }
        ((float4*)out)[(size_t)b * (Vv / 4) + tid] = s;
    }
}

// ---------------------------------------------------------------------------
extern "C" void kernel_launch(void* const* d_in, const int* in_sizes, int n_in,
                              void* d_out, int out_size) {
    const float* x     = (const float*)d_in[0];   // [4096, 1024]
    const float* chars = (const float*)d_in[1];   // [4096, 64, 80]
    const float* W     = (const float*)d_in[2];   // [1024, 30]
    const float* bvec  = (const float*)d_in[3];   // [30]
    float*       out   = (float*)d_out;           // [4096, 80]

    gemm_phi_kernel<<<NBLK, NTHR>>>(x, W, bvec);

    cudaLaunchConfig_t cfg = {};
    cfg.gridDim  = dim3(Bsz, 1, 1);
    cfg.blockDim = dim3(160, 1, 1);
    cfg.dynamicSmemBytes = 0;
    cfg.stream = 0;
    cudaLaunchAttribute attrs[1];
    attrs[0].id = cudaLaunchAttributeProgrammaticStreamSerialization;
    attrs[0].val.programmaticStreamSerializationAllowed = 1;
    cfg.attrs = attrs;
    cfg.numAttrs = 1;
    cudaLaunchKernelEx(&cfg, window_kernel, chars, out);
}